// round 8
// baseline (speedup 1.0000x reference)
#include <cuda_runtime.h>

#define NN 100000
#define EE 1600000
#define GG 128
typedef unsigned long long u64;

__device__ __align__(16) float g_h[NN*128];
__device__ __align__(16) float g_agg[NN*128];
__device__ __align__(16) float g_pre[NN*128];
__device__ float g_rw[NN*16];
__device__ float g_p[2][NN];
__device__ float g_pd[2][NN];
__device__ float g_dinv[NN];
__device__ int   g_ecnt[NN];
__device__ int   g_off[NN+1];
__device__ int   g_cur[NN];
__device__ int   g_src[EE];
__device__ int   g_gcnt[GG];
__device__ float g_stats[10*256];
__device__ __align__(16) float g_bnp[256];
__device__ __align__(16) float g_base[128];
__device__ __align__(16) float g_PW[16*128];
__device__ int g_bsum[512];
__device__ int g_boff[512];

__device__ __forceinline__ u64 pk2(float x){
    u64 r; unsigned xi=__float_as_uint(x);
    asm("mov.b64 %0,{%1,%2};":"=l"(r):"r"(xi),"r"(xi)); return r;
}
__device__ __forceinline__ u64 f2fma(u64 a,u64 b,u64 c){
    u64 d; asm("fma.rn.f32x2 %0,%1,%2,%3;":"=l"(d):"l"(a),"l"(b),"l"(c)); return d;
}
__device__ __forceinline__ float2 unpk(u64 v){
    unsigned lo,hi; asm("mov.b64 {%0,%1},%2;":"=r"(lo),"=r"(hi):"l"(v));
    return make_float2(__uint_as_float(lo),__uint_as_float(hi));
}

__global__ void k_zero(){
    int i=blockIdx.x*256+threadIdx.x;
    if(i<NN) g_ecnt[i]=0;
    if(i<GG) g_gcnt[i]=0;
    if(i<10*256) g_stats[i]=0.f;
}
__global__ void k_hist(const int* __restrict__ col){
    int e=blockIdx.x*256+threadIdx.x;
    if(e<EE) atomicAdd(&g_ecnt[col[e]],1);
}
__global__ void k_bhist(const int* __restrict__ batch){
    int i=blockIdx.x*256+threadIdx.x;
    if(i<NN) atomicAdd(&g_gcnt[batch[i]],1);
}
__global__ void k_scan_block(){
    __shared__ int s[256];
    int i=blockIdx.x*256+threadIdx.x;
    int v=(i<NN)?g_ecnt[i]:0;
    s[threadIdx.x]=v; __syncthreads();
    for(int d=1;d<256;d<<=1){
        int t=(threadIdx.x>=d)?s[threadIdx.x-d]:0;
        __syncthreads(); s[threadIdx.x]+=t; __syncthreads();
    }
    if(i<NN) g_off[i]=s[threadIdx.x]-v;
    if(threadIdx.x==255) g_bsum[blockIdx.x]=s[255];
}
__global__ void k_scan_top(){
    __shared__ int s[512];
    int t=threadIdx.x;
    int v=(t<391)?g_bsum[t]:0;
    s[t]=v; __syncthreads();
    for(int d=1;d<512;d<<=1){
        int x=(t>=d)?s[t-d]:0;
        __syncthreads(); s[t]+=x; __syncthreads();
    }
    g_boff[t]=s[t]-v;
}
__global__ void k_scan_add(){
    int i=blockIdx.x*256+threadIdx.x;
    if(i<NN){ int o=g_off[i]+g_boff[i>>8]; g_off[i]=o; g_cur[i]=o; }
    if(i==0) g_off[NN]=EE;
}
__global__ void k_fill(const int* __restrict__ row,const int* __restrict__ col){
    int e=blockIdx.x*256+threadIdx.x;
    if(e<EE){ int pos=atomicAdd(&g_cur[col[e]],1); g_src[pos]=row[e]; }
}
__global__ void k_dinv(){
    int i=blockIdx.x*256+threadIdx.x;
    if(i<NN) g_dinv[i]=rsqrtf((float)(g_ecnt[i]+1));
}
__global__ void k_prob(const int* __restrict__ batch){
    int i=blockIdx.x*256+threadIdx.x;
    if(i<NN){
        float pv=1.0f/fmaxf((float)g_gcnt[batch[i]],1.0f);
        g_p[0][i]=pv; g_pd[0][i]=pv*g_dinv[i];
    }
}
__global__ void k_init(const float* __restrict__ emb,const float* __restrict__ pe_w,
                       const float* __restrict__ pe_b,const float* __restrict__ pw,
                       const float* __restrict__ pb){
    int j=threadIdx.x;
    float base=pb[j];
    for(int k=0;k<128;k++) base+=emb[k]*pw[k*128+j];
    for(int t=0;t<16;t++)  base+=pe_b[t]*pw[(128+t)*128+j];
    g_base[j]=base;
    for(int t=0;t<16;t++){
        float s=0.f;
        for(int p=0;p<16;p++) s+=pe_w[t*16+p]*pw[(128+p)*128+j];
        g_PW[t*128+j]=s;
    }
}
__global__ void k_rw(int t,int par){
    int c=blockIdx.x*256+threadIdx.x;
    if(c>=NN) return;
    const float* __restrict__ p=g_p[par];
    const float* __restrict__ pd=g_pd[par];
    float pc=p[c];
    g_rw[c*16+t]=pc;
    float s=0.f;
    int b=g_off[c],e=g_off[c+1];
    for(int i=b;i<e;i++) s+=pd[g_src[i]];
    float dc=g_dinv[c];
    float np=(s*dc+pc*dc*dc)*0.9f+pc*0.1f;
    g_p[par^1][c]=np; g_pd[par^1][c]=np*dc;
}
__global__ void k_project(){
    int node=blockIdx.x*8+(threadIdx.x>>5);
    if(node>=NN) return;
    int lane=threadIdx.x&31;
    float4 acc=*(const float4*)&g_base[4*lane];
    const float* rwp=g_rw+node*16;
    #pragma unroll
    for(int t=0;t<16;t++){
        float r=rwp[t];
        float4 w=*(const float4*)&g_PW[t*128+4*lane];
        acc.x+=r*w.x; acc.y+=r*w.y; acc.z+=r*w.z; acc.w+=r*w.w;
    }
    *(float4*)&g_h[(size_t)node*128+4*lane]=acc;
}
__global__ void k_agg(){
    int node=blockIdx.x*8+(threadIdx.x>>5);
    if(node>=NN) return;
    int lane=threadIdx.x&31;
    const float4* hp=(const float4*)g_h;
    float4 acc=hp[(size_t)node*32+lane];
    int b=g_off[node],e=g_off[node+1];
    for(int i=b;i<e;i++){
        float4 v=hp[(size_t)__ldg(&g_src[i])*32+lane];
        acc.x+=v.x; acc.y+=v.y; acc.z+=v.z; acc.w+=v.w;
    }
    ((float4*)g_agg)[(size_t)node*32+lane]=acc;
}

template<int HID,bool RES>
__global__ __launch_bounds__(256) void k_mlp(
    const float* __restrict__ in,float* __restrict__ outp,
    const float* __restrict__ W1,const float* __restrict__ b1,
    const float* __restrict__ W2,const float* __restrict__ b2,
    float* __restrict__ stat)
{
    extern __shared__ float sm[];
    float* s_in=sm;            // [64][128]
    float* s_t =sm+64*128;     // [64][HID]
    float* s_st=s_t+64*HID;    // [256]
    const int tid=threadIdx.x,warp=tid>>5,lane=tid&31;
    const int rbase=warp*8;
    const size_t row0=(size_t)blockIdx.x*64;

    s_st[tid]=0.f;
    {
        const float4* ip=(const float4*)in;
        float4* sp=(float4*)s_in;
        #pragma unroll
        for(int i=0;i<8;i++){
            int idx=tid+256*i;
            size_t grow=row0+(idx>>5);
            if(grow>=NN) grow=NN-1;
            sp[idx]=ip[grow*32+(idx&31)];
        }
    }
    __syncthreads();

    #pragma unroll
    for(int hh=0;hh<HID/128;hh++){
        u64 acc[8][2];
        {
            const u64* bp=(const u64*)(b1+hh*128+4*lane);
            u64 b0=bp[0],bb=bp[1];
            #pragma unroll
            for(int r=0;r<8;r++){acc[r][0]=b0;acc[r][1]=bb;}
        }
        #pragma unroll 4
        for(int k=0;k<128;k++){
            ulonglong2 w=*(const ulonglong2*)(W1+(size_t)k*HID+hh*128+4*lane);
            #pragma unroll
            for(int r=0;r<8;r++){
                u64 a=pk2(s_in[(rbase+r)*128+k]);
                acc[r][0]=f2fma(a,w.x,acc[r][0]);
                acc[r][1]=f2fma(a,w.y,acc[r][1]);
            }
        }
        #pragma unroll
        for(int r=0;r<8;r++){
            float2 f01=unpk(acc[r][0]),f23=unpk(acc[r][1]);
            float4 v;
            v.x=fmaxf(f01.x,0.f); v.y=fmaxf(f01.y,0.f);
            v.z=fmaxf(f23.x,0.f); v.w=fmaxf(f23.y,0.f);
            *(float4*)&s_t[(rbase+r)*HID+hh*128+4*lane]=v;
        }
    }
    __syncwarp();

    u64 oacc[8][2];
    {
        const u64* bp=(const u64*)(b2+4*lane);
        u64 b0=bp[0],bb=bp[1];
        #pragma unroll
        for(int r=0;r<8;r++){oacc[r][0]=b0;oacc[r][1]=bb;}
    }
    #pragma unroll 4
    for(int k=0;k<HID;k++){
        ulonglong2 w=*(const ulonglong2*)(W2+(size_t)k*128+4*lane);
        #pragma unroll
        for(int r=0;r<8;r++){
            u64 a=pk2(s_t[(rbase+r)*HID+k]);
            oacc[r][0]=f2fma(a,w.x,oacc[r][0]);
            oacc[r][1]=f2fma(a,w.y,oacc[r][1]);
        }
    }
    float cs[4]={0,0,0,0},cq[4]={0,0,0,0};
    #pragma unroll
    for(int r=0;r<8;r++){
        size_t grow=row0+rbase+r;
        if(grow>=NN) break;
        float2 f01=unpk(oacc[r][0]),f23=unpk(oacc[r][1]);
        float4 o; o.x=f01.x; o.y=f01.y; o.z=f23.x; o.w=f23.y;
        if(RES){
            float4 iv=*(const float4*)&s_in[(rbase+r)*128+4*lane];
            o.x+=iv.x; o.y+=iv.y; o.z+=iv.z; o.w+=iv.w;
        }
        ((float4*)outp)[grow*32+lane]=o;
        cs[0]+=o.x; cs[1]+=o.y; cs[2]+=o.z; cs[3]+=o.w;
        cq[0]+=o.x*o.x; cq[1]+=o.y*o.y; cq[2]+=o.z*o.z; cq[3]+=o.w*o.w;
    }
    #pragma unroll
    for(int i=0;i<4;i++){
        atomicAdd(&s_st[4*lane+i],cs[i]);
        atomicAdd(&s_st[128+4*lane+i],cq[i]);
    }
    __syncthreads();
    atomicAdd(&stat[tid],s_st[tid]);
}

__global__ void k_bnfin(const float* __restrict__ stat,const float* __restrict__ gg,
                        const float* __restrict__ bb){
    int j=threadIdx.x;
    float sum=stat[j],sq=stat[128+j];
    float mu=sum/(float)NN;
    float var=fmaxf(sq/(float)NN-mu*mu,0.f);
    float sc=gg[j]*rsqrtf(var+1e-5f);
    g_bnp[j]=sc;
    g_bnp[128+j]=bb[j]-mu*sc;
}
__global__ void k_bn1(){
    int idx=blockIdx.x*256+threadIdx.x;
    if(idx>=NN*32) return;
    float4 z=((const float4*)g_pre)[idx];
    int j=(idx&31)*4;
    float4 sc=*(const float4*)&g_bnp[j];
    float4 sh=*(const float4*)&g_bnp[128+j];
    float4* hp=(float4*)g_h;
    float4 hv=hp[idx];
    hv.x+=fmaxf(z.x*sc.x+sh.x,0.f);
    hv.y+=fmaxf(z.y*sc.y+sh.y,0.f);
    hv.z+=fmaxf(z.z*sc.z+sh.z,0.f);
    hv.w+=fmaxf(z.w*sc.w+sh.w,0.f);
    hp[idx]=hv;
}
__global__ void k_bn2(){
    int idx=blockIdx.x*256+threadIdx.x;
    if(idx>=NN*32) return;
    float4 z=((const float4*)g_pre)[idx];
    int j=(idx&31)*4;
    float4 sc=*(const float4*)&g_bnp[j];
    float4 sh=*(const float4*)&g_bnp[128+j];
    float4 hv;
    hv.x=z.x*sc.x+sh.x; hv.y=z.y*sc.y+sh.y;
    hv.z=z.z*sc.z+sh.z; hv.w=z.w*sc.w+sh.w;
    ((float4*)g_h)[idx]=hv;
}

__device__ __forceinline__ int lbound(const int* a,int n,int v){
    int lo=0,hi=n;
    while(lo<hi){int m=(lo+hi)>>1; if(a[m]<v) lo=m+1; else hi=m;}
    return lo;
}
__global__ void k_head(const int* __restrict__ batch,
                       const float* __restrict__ w1,const float* __restrict__ b1,
                       const float* __restrict__ w2,const float* __restrict__ b2,
                       float* __restrict__ out){
    int g=blockIdx.x,j=threadIdx.x;
    int st=lbound(batch,NN,g),en=lbound(batch,NN,g+1);
    float s=0.f;
    for(int i=st;i<en;i++) s+=g_h[(size_t)i*128+j];
    __shared__ float sg[128],stt[128];
    sg[j]=s/fmaxf((float)(en-st),1.f);
    __syncthreads();
    float t=b1[j];
    for(int k=0;k<128;k++) t+=sg[k]*w1[k*128+j];
    stt[j]=fmaxf(t,0.f);
    __syncthreads();
    if(j<10){
        float o=b2[j];
        for(int k=0;k<128;k++) o+=stt[k]*w2[k*10+j];
        out[g*10+j]=o;
    }
}

extern "C" void kernel_launch(void* const* d_in,const int* in_sizes,int n_in,
                              void* d_out,int out_size){
    const int* edge=(const int*)d_in[1];
    const int* erow=edge;
    const int* ecol=edge+EE;
    const int* batch=(const int*)d_in[2];
    const float* emb=(const float*)d_in[3];
    const float* pe_w=(const float*)d_in[4];
    const float* pe_b=(const float*)d_in[5];
    const float* proj_w=(const float*)d_in[6];
    const float* proj_b=(const float*)d_in[7];
    const float* gw1=(const float*)d_in[8];
    const float* gb1=(const float*)d_in[9];
    const float* gw2=(const float*)d_in[10];
    const float* gb2=(const float*)d_in[11];
    const float* bng=(const float*)d_in[12];
    const float* bnb=(const float*)d_in[13];
    const float* fw1=(const float*)d_in[14];
    const float* fb1=(const float*)d_in[15];
    const float* fw2=(const float*)d_in[16];
    const float* fb2=(const float*)d_in[17];
    const float* fbng=(const float*)d_in[18];
    const float* fbnb=(const float*)d_in[19];
    const float* ow1=(const float*)d_in[20];
    const float* ob1=(const float*)d_in[21];
    const float* ow2=(const float*)d_in[22];
    const float* ob2=(const float*)d_in[23];

    float *p_h,*p_agg,*p_pre,*p_stats;
    cudaGetSymbolAddress((void**)&p_h,g_h);
    cudaGetSymbolAddress((void**)&p_agg,g_agg);
    cudaGetSymbolAddress((void**)&p_pre,g_pre);
    cudaGetSymbolAddress((void**)&p_stats,g_stats);

    const int SM128=(64*128+64*128+256)*4;
    const int SM256=(64*128+64*256+256)*4;
    cudaFuncSetAttribute(k_mlp<128,false>,cudaFuncAttributeMaxDynamicSharedMemorySize,SM128);
    cudaFuncSetAttribute(k_mlp<256,true>, cudaFuncAttributeMaxDynamicSharedMemorySize,SM256);

    const int NB=(NN+255)/256;
    const int EB=(EE+255)/256;
    const int WB=(NN+7)/8;
    const int VB=(NN*32+255)/256;
    const int MB=(NN+63)/64;

    k_zero<<<NB,256>>>();
    k_hist<<<EB,256>>>(ecol);
    k_bhist<<<NB,256>>>(batch);
    k_scan_block<<<NB,256>>>();
    k_scan_top<<<1,512>>>();
    k_scan_add<<<NB,256>>>();
    k_fill<<<EB,256>>>(erow,ecol);
    k_dinv<<<NB,256>>>();
    k_prob<<<NB,256>>>(batch);
    k_init<<<1,128>>>(emb,pe_w,pe_b,proj_w,proj_b);

    for(int t=0;t<16;t++) k_rw<<<NB,256>>>(t,t&1);

    k_project<<<WB,256>>>();

    for(int l=0;l<5;l++){
        k_agg<<<WB,256>>>();
        k_mlp<128,false><<<MB,256,SM128>>>(p_agg,p_pre,
            gw1+(size_t)l*128*128,gb1+l*128,
            gw2+(size_t)l*128*128,gb2+l*128,
            p_stats+(2*l)*256);
        k_bnfin<<<1,128>>>(p_stats+(2*l)*256,bng+l*128,bnb+l*128);
        k_bn1<<<VB,256>>>();
        k_mlp<256,true><<<MB,256,SM256>>>(p_h,p_pre,
            fw1+(size_t)l*128*256,fb1+l*256,
            fw2+(size_t)l*256*128,fb2+l*128,
            p_stats+(2*l+1)*256);
        k_bnfin<<<1,128>>>(p_stats+(2*l+1)*256,fbng+l*128,fbnb+l*128);
        k_bn2<<<VB,256>>>();
    }

    k_head<<<GG,128>>>(batch,ow1,ob1,ow2,ob2,(float*)d_out);
}